// round 4
// baseline (speedup 1.0000x reference)
#include <cuda_runtime.h>

#define D    64
#define K    1024
#define KC   128          // codes per shared-memory chunk
#define TPB  128

__device__ float g_cnorm[K];   // ||e_k||^2 per code

// Precompute per-code squared norms. Coalesced: threads stride over k.
__global__ void cnorm_kernel(const float* __restrict__ e)
{
    int k = blockIdx.x * blockDim.x + threadIdx.x;
    if (k < K) {
        float s = 0.0f;
        #pragma unroll
        for (int i = 0; i < D; ++i) {
            float v = e[i * K + k];
            s = fmaf(v, v, s);
        }
        g_cnorm[k] = s;
    }
}

// One pixel per thread. x-vector in registers, codebook chunks in shared,
// dot products via packed fma.rn.f32x2 (2 codes per instruction).
__global__ __launch_bounds__(TPB)
void vq_kernel(const float* __restrict__ x,
               const float* __restrict__ e,
               float* __restrict__ out)
{
    __shared__ __align__(16) float sE[D][KC];  // sE[i][kk] = e[i][k0+kk]
    __shared__ float sC[KC];

    const int tid = threadIdx.x;
    const int p   = blockIdx.x * TPB + tid;    // pixel id, 0..65535
    const int b   = p >> 12;                   // 4096 pixels per batch image
    const int hw  = p & 4095;
    const int xbase = b * (D * 4096) + hw;     // x[b, c, h, w] = x[xbase + c*4096]

    // Load this pixel's 64-dim vector into registers (coalesced per channel).
    float xr[D];
    #pragma unroll
    for (int c = 0; c < D; ++c)
        xr[c] = x[xbase + c * 4096];

    float best    = 3.4e38f;
    int   bestIdx = 0;

    for (int k0 = 0; k0 < K; k0 += KC) {
        // Cooperative chunk load: row n of codebook, 128 consecutive codes.
        #pragma unroll 8
        for (int n = 0; n < D; ++n)
            sE[n][tid] = e[n * K + k0 + tid];
        sC[tid] = g_cnorm[k0 + tid];
        __syncthreads();

        // Process 16 codes at a time: 8 packed-f32x2 accumulators.
        for (int kk = 0; kk < KC; kk += 16) {
            unsigned long long acc[8];
            #pragma unroll
            for (int j = 0; j < 8; ++j) acc[j] = 0ULL;   // {+0.f, +0.f}

            #pragma unroll
            for (int i = 0; i < D; ++i) {
                unsigned long long xx;
                asm("mov.b64 %0, {%1, %1};"
                    : "=l"(xx) : "r"(__float_as_uint(xr[i])));
                const ulonglong2* ep =
                    reinterpret_cast<const ulonglong2*>(&sE[i][kk]);
                ulonglong2 e0 = ep[0];
                ulonglong2 e1 = ep[1];
                ulonglong2 e2 = ep[2];
                ulonglong2 e3 = ep[3];
                asm("fma.rn.f32x2 %0, %1, %2, %0;" : "+l"(acc[0]) : "l"(xx), "l"(e0.x));
                asm("fma.rn.f32x2 %0, %1, %2, %0;" : "+l"(acc[1]) : "l"(xx), "l"(e0.y));
                asm("fma.rn.f32x2 %0, %1, %2, %0;" : "+l"(acc[2]) : "l"(xx), "l"(e1.x));
                asm("fma.rn.f32x2 %0, %1, %2, %0;" : "+l"(acc[3]) : "l"(xx), "l"(e1.y));
                asm("fma.rn.f32x2 %0, %1, %2, %0;" : "+l"(acc[4]) : "l"(xx), "l"(e2.x));
                asm("fma.rn.f32x2 %0, %1, %2, %0;" : "+l"(acc[5]) : "l"(xx), "l"(e2.y));
                asm("fma.rn.f32x2 %0, %1, %2, %0;" : "+l"(acc[6]) : "l"(xx), "l"(e3.x));
                asm("fma.rn.f32x2 %0, %1, %2, %0;" : "+l"(acc[7]) : "l"(xx), "l"(e3.y));
            }

            // dist_k = ||e_k||^2 - 2 * (x . e_k); strict '<' with ascending k
            // keeps the first (lowest) index on ties, matching jnp.argmin.
            #pragma unroll
            for (int j = 0; j < 8; ++j) {
                float d0, d1;
                asm("mov.b64 {%0, %1}, %2;" : "=f"(d0), "=f"(d1) : "l"(acc[j]));
                float dist0 = sC[kk + 2 * j]     - 2.0f * d0;
                float dist1 = sC[kk + 2 * j + 1] - 2.0f * d1;
                if (dist0 < best) { best = dist0; bestIdx = k0 + kk + 2 * j; }
                if (dist1 < best) { best = dist1; bestIdx = k0 + kk + 2 * j + 1; }
            }
        }
        __syncthreads();
    }

    // Gather winning code vector back to (B, C, H, W). Stores coalesced;
    // codebook gathers hit L2/L1 (256 KB working set).
    #pragma unroll
    for (int c = 0; c < D; ++c)
        out[xbase + c * 4096] = __ldg(&e[c * K + bestIdx]);
}

extern "C" void kernel_launch(void* const* d_in, const int* in_sizes, int n_in,
                              void* d_out, int out_size)
{
    // metadata order: d_in[0] = x (4194304 f32), d_in[1] = e_i_ts (65536 f32).
    // Be robust to ordering via element counts.
    const float* x = (const float*)d_in[0];
    const float* e = (const float*)d_in[1];
    if (n_in >= 2 && in_sizes[0] == D * K && in_sizes[1] == 16 * D * 64 * 64) {
        x = (const float*)d_in[1];
        e = (const float*)d_in[0];
    }
    float* out = (float*)d_out;

    cnorm_kernel<<<(K + 127) / 128, 128>>>(e);
    vq_kernel<<<65536 / TPB, TPB>>>(x, e, out);
}

// round 5
// speedup vs baseline: 1.3007x; 1.3007x over previous
#include <cuda_runtime.h>

#define D    64
#define K    1024
#define KC   128          // codes per shared-memory chunk
#define TPB  128
#define PIX  2            // pixels per thread

__device__ float g_cnorm[K];   // ||e_k||^2 per code

__global__ void cnorm_kernel(const float* __restrict__ e)
{
    int k = blockIdx.x * blockDim.x + threadIdx.x;
    if (k < K) {
        float s = 0.0f;
        #pragma unroll
        for (int i = 0; i < D; ++i) {
            float v = e[i * K + k];
            s = fmaf(v, v, s);
        }
        g_cnorm[k] = s;
    }
}

// Two pixels per thread: each codebook pair loaded from shared feeds FFMA2s
// for both pixels, halving LDS traffic per FLOP vs the 1-pixel version.
__global__ __launch_bounds__(TPB, 2)
void vq_kernel(const float* __restrict__ x,
               const float* __restrict__ e,
               float* __restrict__ out)
{
    __shared__ __align__(16) float sE[D][KC];  // sE[i][kk] = e[i][k0+kk]
    __shared__ float sC[KC];

    const int tid = threadIdx.x;
    const int p0  = blockIdx.x * (TPB * PIX) + tid;  // pixel A
    const int p1  = p0 + TPB;                        // pixel B
    // 4096 pixels per batch image; a block's 256-pixel span never crosses an
    // image boundary (256 | 4096), but compute bases independently anyway.
    const int xbase0 = (p0 >> 12) * (D * 4096) + (p0 & 4095);
    const int xbase1 = (p1 >> 12) * (D * 4096) + (p1 & 4095);

    // Both pixels' 64-dim vectors in registers (~128 regs).
    float xr0[D], xr1[D];
    #pragma unroll
    for (int c = 0; c < D; ++c) {
        xr0[c] = x[xbase0 + c * 4096];
        xr1[c] = x[xbase1 + c * 4096];
    }

    float best0 = 3.4e38f, best1 = 3.4e38f;
    int   bi0 = 0,         bi1 = 0;

    for (int k0 = 0; k0 < K; k0 += KC) {
        #pragma unroll 8
        for (int n = 0; n < D; ++n)
            sE[n][tid] = e[n * K + k0 + tid];
        sC[tid] = g_cnorm[k0 + tid];
        __syncthreads();

        // 16 codes per group: 8 packed-pair accumulators per pixel.
        for (int kk = 0; kk < KC; kk += 16) {
            unsigned long long a0[8], a1[8];
            #pragma unroll
            for (int j = 0; j < 8; ++j) { a0[j] = 0ULL; a1[j] = 0ULL; }

            #pragma unroll 16
            for (int i = 0; i < D; ++i) {
                unsigned long long xx0, xx1;
                asm("mov.b64 %0, {%1, %1};"
                    : "=l"(xx0) : "r"(__float_as_uint(xr0[i])));
                asm("mov.b64 %0, {%1, %1};"
                    : "=l"(xx1) : "r"(__float_as_uint(xr1[i])));
                const ulonglong2* ep =
                    reinterpret_cast<const ulonglong2*>(&sE[i][kk]);
                ulonglong2 e0 = ep[0];
                ulonglong2 e1 = ep[1];
                ulonglong2 e2 = ep[2];
                ulonglong2 e3 = ep[3];
                asm("fma.rn.f32x2 %0, %1, %2, %0;" : "+l"(a0[0]) : "l"(xx0), "l"(e0.x));
                asm("fma.rn.f32x2 %0, %1, %2, %0;" : "+l"(a1[0]) : "l"(xx1), "l"(e0.x));
                asm("fma.rn.f32x2 %0, %1, %2, %0;" : "+l"(a0[1]) : "l"(xx0), "l"(e0.y));
                asm("fma.rn.f32x2 %0, %1, %2, %0;" : "+l"(a1[1]) : "l"(xx1), "l"(e0.y));
                asm("fma.rn.f32x2 %0, %1, %2, %0;" : "+l"(a0[2]) : "l"(xx0), "l"(e1.x));
                asm("fma.rn.f32x2 %0, %1, %2, %0;" : "+l"(a1[2]) : "l"(xx1), "l"(e1.x));
                asm("fma.rn.f32x2 %0, %1, %2, %0;" : "+l"(a0[3]) : "l"(xx0), "l"(e1.y));
                asm("fma.rn.f32x2 %0, %1, %2, %0;" : "+l"(a1[3]) : "l"(xx1), "l"(e1.y));
                asm("fma.rn.f32x2 %0, %1, %2, %0;" : "+l"(a0[4]) : "l"(xx0), "l"(e2.x));
                asm("fma.rn.f32x2 %0, %1, %2, %0;" : "+l"(a1[4]) : "l"(xx1), "l"(e2.x));
                asm("fma.rn.f32x2 %0, %1, %2, %0;" : "+l"(a0[5]) : "l"(xx0), "l"(e2.y));
                asm("fma.rn.f32x2 %0, %1, %2, %0;" : "+l"(a1[5]) : "l"(xx1), "l"(e2.y));
                asm("fma.rn.f32x2 %0, %1, %2, %0;" : "+l"(a0[6]) : "l"(xx0), "l"(e3.x));
                asm("fma.rn.f32x2 %0, %1, %2, %0;" : "+l"(a1[6]) : "l"(xx1), "l"(e3.x));
                asm("fma.rn.f32x2 %0, %1, %2, %0;" : "+l"(a0[7]) : "l"(xx0), "l"(e3.y));
                asm("fma.rn.f32x2 %0, %1, %2, %0;" : "+l"(a1[7]) : "l"(xx1), "l"(e3.y));
            }

            // dist_k = ||e_k||^2 - 2*(x.e_k); strict '<' over ascending k keeps
            // the first index on ties, matching jnp.argmin.
            #pragma unroll
            for (int j = 0; j < 8; ++j) {
                float cA = sC[kk + 2 * j];
                float cB = sC[kk + 2 * j + 1];
                float d0, d1;
                asm("mov.b64 {%0, %1}, %2;" : "=f"(d0), "=f"(d1) : "l"(a0[j]));
                float s0 = fmaf(-2.0f, d0, cA);
                float s1 = fmaf(-2.0f, d1, cB);
                if (s0 < best0) { best0 = s0; bi0 = k0 + kk + 2 * j; }
                if (s1 < best0) { best0 = s1; bi0 = k0 + kk + 2 * j + 1; }
                asm("mov.b64 {%0, %1}, %2;" : "=f"(d0), "=f"(d1) : "l"(a1[j]));
                s0 = fmaf(-2.0f, d0, cA);
                s1 = fmaf(-2.0f, d1, cB);
                if (s0 < best1) { best1 = s0; bi1 = k0 + kk + 2 * j; }
                if (s1 < best1) { best1 = s1; bi1 = k0 + kk + 2 * j + 1; }
            }
        }
        __syncthreads();
    }

    // Gather winning code vectors; stores coalesced, codebook gathers hit L2.
    #pragma unroll
    for (int c = 0; c < D; ++c) {
        out[xbase0 + c * 4096] = __ldg(&e[c * K + bi0]);
        out[xbase1 + c * 4096] = __ldg(&e[c * K + bi1]);
    }
}

extern "C" void kernel_launch(void* const* d_in, const int* in_sizes, int n_in,
                              void* d_out, int out_size)
{
    const float* x = (const float*)d_in[0];
    const float* e = (const float*)d_in[1];
    if (n_in >= 2 && in_sizes[0] == D * K && in_sizes[1] == 16 * D * 64 * 64) {
        x = (const float*)d_in[1];
        e = (const float*)d_in[0];
    }
    float* out = (float*)d_out;

    cnorm_kernel<<<(K + 127) / 128, 128>>>(e);
    vq_kernel<<<65536 / (TPB * PIX), TPB>>>(x, e, out);
}

// round 7
// speedup vs baseline: 1.5237x; 1.1715x over previous
#include <cuda_runtime.h>

#define D    64
#define K    1024
#define KC   128          // codes per shared-memory chunk
#define TPB  128
#define PIX  2            // pixels per thread

__device__ float g_cnorm[K];   // ||e_k||^2 per code

__global__ void cnorm_kernel(const float* __restrict__ e)
{
    int k = blockIdx.x * blockDim.x + threadIdx.x;
    if (k < K) {
        float s = 0.0f;
        #pragma unroll
        for (int i = 0; i < D; ++i) {
            float v = e[i * K + k];
            s = fmaf(v, v, s);
        }
        g_cnorm[k] = s;
    }
}

#define FMA2(acc, a, b) \
    asm("fma.rn.f32x2 %0, %1, %2, %0;" : "+l"(acc) : "l"(a), "l"(b))

// Two pixels per thread; channel loop software-pipelined: e-vector loads for
// iteration i+1 issue while iteration i's 16 FFMA2s execute, hiding the
// ~29-cycle LDS latency that bound the previous version.
__global__ __launch_bounds__(TPB, 2)
void vq_kernel(const float* __restrict__ x,
               const float* __restrict__ e,
               float* __restrict__ out)
{
    __shared__ __align__(16) float sE[D][KC];  // sE[i][kk] = e[i][k0+kk]
    __shared__ float sC[KC];

    const int tid = threadIdx.x;
    const int p0  = blockIdx.x * (TPB * PIX) + tid;  // pixel A
    const int p1  = p0 + TPB;                        // pixel B
    const int xbase0 = (p0 >> 12) * (D * 4096) + (p0 & 4095);
    const int xbase1 = (p1 >> 12) * (D * 4096) + (p1 & 4095);

    // Both pixels' 64-dim vectors in registers (~128 regs).
    float xr0[D], xr1[D];
    #pragma unroll
    for (int c = 0; c < D; ++c) {
        xr0[c] = x[xbase0 + c * 4096];
        xr1[c] = x[xbase1 + c * 4096];
    }

    float best0 = 3.4e38f, best1 = 3.4e38f;
    int   bi0 = 0,         bi1 = 0;

    for (int k0 = 0; k0 < K; k0 += KC) {
        // Vectorized chunk fill: D*KC floats = 2048 float4, 16 per thread.
        #pragma unroll
        for (int pass = 0; pass < (D * KC / 4) / TPB; ++pass) {
            int idx = pass * TPB + tid;    // 0..2047
            int n   = idx >> 5;            // row (channel), 32 float4 per row
            int c4  = idx & 31;
            float4 v = *reinterpret_cast<const float4*>(&e[n * K + k0 + c4 * 4]);
            *reinterpret_cast<float4*>(&sE[n][c4 * 4]) = v;
        }
        sC[tid] = g_cnorm[k0 + tid];
        __syncthreads();

        // 16 codes per group: 8 packed-pair accumulators per pixel.
        for (int kk = 0; kk < KC; kk += 16) {
            unsigned long long a0[8], a1[8];
            #pragma unroll
            for (int j = 0; j < 8; ++j) { a0[j] = 0ULL; a1[j] = 0ULL; }

            // Prime the pipeline: loads for channel 0.
            ulonglong2 cur[4], nxt[4];
            {
                const ulonglong2* ep =
                    reinterpret_cast<const ulonglong2*>(&sE[0][kk]);
                cur[0] = ep[0]; cur[1] = ep[1]; cur[2] = ep[2]; cur[3] = ep[3];
            }

            #pragma unroll
            for (int i = 0; i < D; ++i) {
                // Prefetch channel i+1 before consuming channel i.
                if (i + 1 < D) {
                    const ulonglong2* ep =
                        reinterpret_cast<const ulonglong2*>(&sE[i + 1][kk]);
                    nxt[0] = ep[0]; nxt[1] = ep[1];
                    nxt[2] = ep[2]; nxt[3] = ep[3];
                }
                unsigned long long xx0, xx1;
                asm("mov.b64 %0, {%1, %1};"
                    : "=l"(xx0) : "r"(__float_as_uint(xr0[i])));
                asm("mov.b64 %0, {%1, %1};"
                    : "=l"(xx1) : "r"(__float_as_uint(xr1[i])));

                FMA2(a0[0], xx0, cur[0].x);  FMA2(a1[0], xx1, cur[0].x);
                FMA2(a0[1], xx0, cur[0].y);  FMA2(a1[1], xx1, cur[0].y);
                FMA2(a0[2], xx0, cur[1].x);  FMA2(a1[2], xx1, cur[1].x);
                FMA2(a0[3], xx0, cur[1].y);  FMA2(a1[3], xx1, cur[1].y);
                FMA2(a0[4], xx0, cur[2].x);  FMA2(a1[4], xx1, cur[2].x);
                FMA2(a0[5], xx0, cur[2].y);  FMA2(a1[5], xx1, cur[2].y);
                FMA2(a0[6], xx0, cur[3].x);  FMA2(a1[6], xx1, cur[3].x);
                FMA2(a0[7], xx0, cur[3].y);  FMA2(a1[7], xx1, cur[3].y);

                if (i + 1 < D) {
                    cur[0] = nxt[0]; cur[1] = nxt[1];
                    cur[2] = nxt[2]; cur[3] = nxt[3];
                }
            }

            // dist_k = ||e_k||^2 - 2*(x.e_k); strict '<' over ascending k keeps
            // the first index on ties, matching jnp.argmin.
            #pragma unroll
            for (int j = 0; j < 8; ++j) {
                float cA = sC[kk + 2 * j];
                float cB = sC[kk + 2 * j + 1];
                float d0, d1;
                asm("mov.b64 {%0, %1}, %2;" : "=f"(d0), "=f"(d1) : "l"(a0[j]));
                float s0 = fmaf(-2.0f, d0, cA);
                float s1 = fmaf(-2.0f, d1, cB);
                if (s0 < best0) { best0 = s0; bi0 = k0 + kk + 2 * j; }
                if (s1 < best0) { best0 = s1; bi0 = k0 + kk + 2 * j + 1; }
                asm("mov.b64 {%0, %1}, %2;" : "=f"(d0), "=f"(d1) : "l"(a1[j]));
                s0 = fmaf(-2.0f, d0, cA);
                s1 = fmaf(-2.0f, d1, cB);
                if (s0 < best1) { best1 = s0; bi1 = k0 + kk + 2 * j; }
                if (s1 < best1) { best1 = s1; bi1 = k0 + kk + 2 * j + 1; }
            }
        }
        __syncthreads();
    }

    // Gather winning code vectors; stores coalesced, codebook gathers hit L2.
    #pragma unroll
    for (int c = 0; c < D; ++c) {
        out[xbase0 + c * 4096] = __ldg(&e[c * K + bi0]);
        out[xbase1 + c * 4096] = __ldg(&e[c * K + bi1]);
    }
}

extern "C" void kernel_launch(void* const* d_in, const int* in_sizes, int n_in,
                              void* d_out, int out_size)
{
    const float* x = (const float*)d_in[0];
    const float* e = (const float*)d_in[1];
    if (n_in >= 2 && in_sizes[0] == D * K && in_sizes[1] == 16 * D * 64 * 64) {
        x = (const float*)d_in[1];
        e = (const float*)d_in[0];
    }
    float* out = (float*)d_out;

    cnorm_kernel<<<(K + 127) / 128, 128>>>(e);
    vq_kernel<<<65536 / (TPB * PIX), TPB>>>(x, e, out);
}